// round 16
// baseline (speedup 1.0000x reference)
#include <cuda_runtime.h>
#include <cuda_fp16.h>
#include <cstdint>
#include <math.h>

// Problem constants
#define B_  4
#define T_  4096
#define D_  512
#define BT_ (B_ * T_)          // 16384
#define N3_ (3 * D_)           // 1536
#define EPS_LN 1e-5f
#define SCALE_QK 0.04419417382415922f   // 1/sqrt(512)

typedef long long ll;
typedef __half fp16;

// ---------------- scratch (device globals) ----------------------------------
__device__ fp16  g_xn16 [(ll)BT_ * D_];       // LN output fp16
__device__ fp16  g_wqkvT16 [(ll)N3_ * D_];    // Wqkv^T fp16
__device__ fp16  g_wprojT16[(ll)D_ * D_];     // Wproj^T fp16
__device__ fp16  g_qkv16[(ll)BT_ * N3_];      // Q,K,V fp16
__device__ fp16  g_vt16 [(ll)B_ * D_ * T_];   // V transposed fp16
__device__ float g_S    [(ll)B_ * T_ * T_];   // scores f32
__device__ fp16  g_P16  [(ll)B_ * T_ * T_];   // probs fp16
__device__ fp16  g_att16[(ll)BT_ * D_];       // attention out fp16

// ---------------- PTX helpers (all base sm_103-safe) -------------------------
__device__ __forceinline__ uint32_t smem_u32(const void* p) {
    uint32_t a;
    asm("{ .reg .u64 t; cvta.to.shared.u64 t, %1; cvt.u32.u64 %0, t; }" : "=r"(a) : "l"(p));
    return a;
}
__device__ __forceinline__ void cp16(uint32_t d, const void* g) {
    asm volatile("cp.async.cg.shared.global [%0], [%1], 16;" :: "r"(d), "l"(g) : "memory");
}
#define CP_COMMIT() asm volatile("cp.async.commit_group;" ::: "memory")
#define CP_WAIT(n)  asm volatile("cp.async.wait_group %0;" :: "n"(n) : "memory")

#define LDSM4(r0, r1, r2, r3, a) \
    asm volatile("ldmatrix.sync.aligned.m8n8.x4.shared.b16 {%0,%1,%2,%3}, [%4];" \
        : "=r"(r0), "=r"(r1), "=r"(r2), "=r"(r3) : "r"(a))

#define MMA16816H(d, a, b) \
    asm volatile("mma.sync.aligned.m16n8k16.row.col.f32.f16.f16.f32 " \
        "{%0,%1,%2,%3}, {%4,%5,%6,%7}, {%8,%9}, {%0,%1,%2,%3};" \
        : "+f"((d)[0]), "+f"((d)[1]), "+f"((d)[2]), "+f"((d)[3]) \
        : "r"((a)[0]), "r"((a)[1]), "r"((a)[2]), "r"((a)[3]), "r"((b)[0]), "r"((b)[1]))

// ---------------- LayerNorm -> fp16 ------------------------------------------
__global__ void ln_kernel(const float* __restrict__ x,
                          const float* __restrict__ gamma,
                          const float* __restrict__ beta,
                          fp16* __restrict__ xn)
{
    const ll row = blockIdx.x;
    const int tid = threadIdx.x;             // 0..127
    float4 v = ((const float4*)(x + row * D_))[tid];

    float s  = v.x + v.y + v.z + v.w;
    float ss = v.x*v.x + v.y*v.y + v.z*v.z + v.w*v.w;
    #pragma unroll
    for (int o = 16; o > 0; o >>= 1) {
        s  += __shfl_xor_sync(0xffffffffu, s,  o);
        ss += __shfl_xor_sync(0xffffffffu, ss, o);
    }
    __shared__ float rs[4], rss[4];
    if ((tid & 31) == 0) { rs[tid >> 5] = s; rss[tid >> 5] = ss; }
    __syncthreads();
    s  = rs[0] + rs[1] + rs[2] + rs[3];
    ss = rss[0] + rss[1] + rss[2] + rss[3];

    const float mu   = s * (1.0f / D_);
    const float var  = ss * (1.0f / D_) - mu * mu;
    const float rstd = rsqrtf(var + EPS_LN);

    float4 g = ((const float4*)gamma)[tid];
    float4 b = ((const float4*)beta)[tid];
    __half2 h2[2];
    h2[0] = __floats2half2_rn((v.x - mu) * rstd * g.x + b.x,
                              (v.y - mu) * rstd * g.y + b.y);
    h2[1] = __floats2half2_rn((v.z - mu) * rstd * g.z + b.z,
                              (v.w - mu) * rstd * g.w + b.w);
    *(ulonglong1*)(xn + row * D_ + tid * 4) = *(ulonglong1*)h2;
}

// ---------------- weight transpose-convert: W[K,N] f32 -> Wt[N,K] fp16 -------
__global__ void wtrans_kernel(const float* __restrict__ W, int K, int N,
                              fp16* __restrict__ Tw)
{
    __shared__ float t[32][33];
    const int n0 = blockIdx.x * 32, k0 = blockIdx.y * 32;
    const int tx = threadIdx.x, ty = threadIdx.y;
    #pragma unroll
    for (int i = 0; i < 32; i += 8)
        t[ty + i][tx] = W[(ll)(k0 + ty + i) * N + n0 + tx];
    __syncthreads();
    #pragma unroll
    for (int i = 0; i < 32; i += 8)
        Tw[(ll)(n0 + ty + i) * K + k0 + tx] = __float2half_rn(t[tx][ty + i]);
}

// ---------------- V transpose: qkv16 [BT,1536] -> VT fp16 [B,512,T] ----------
__global__ void vtrans_kernel(const fp16* __restrict__ q16, fp16* __restrict__ vt)
{
    __shared__ fp16 t[32][33];
    const int s0 = blockIdx.x * 32, c0 = blockIdx.y * 32, b = blockIdx.z;
    const int tx = threadIdx.x, ty = threadIdx.y;
    const ll qb = ((ll)b * T_) * N3_ + 2 * D_;
    #pragma unroll
    for (int i = 0; i < 32; i += 8)
        t[ty + i][tx] = q16[qb + (ll)(s0 + ty + i) * N3_ + c0 + tx];
    __syncthreads();
    const ll vb = (ll)b * D_ * T_;
    #pragma unroll
    for (int i = 0; i < 32; i += 8)
        vt[vb + (ll)(c0 + ty + i) * T_ + s0 + tx] = t[tx][ty + i];
}

// ---------------- fp16 x1 NT GEMM, CTA 64x128, BK=64, warp tile 32x32 --------
// C[M,N] = alpha * A[M,K] @ B[N,K]^T, fp16 operands, fp32 accum.
// flags: 1 = causal tile skip (2*bx > by), 2 = causal kbound, 8 = fp16 output
// 8 warps as 2(M) x 4(N); 2x4 grid of m16n8k16 per warp; BK=64 chunks,
// 3-stage cp.async (24 KB/stage), 3 CTAs/SM (24 warps).
#define MAT_A 8192                 // 64 rows * 64 k * 2B
#define MAT_BB 16384               // 128 rows * 64 k * 2B
#define NSTAGE 3
#define STG16_B (MAT_A + MAT_BB)   // 24 KB
#define GSMEM16 (NSTAGE * STG16_B) // 72 KB

__global__ __launch_bounds__(256, 3)
void gemm_mma16(const fp16* __restrict__ A, int lda, ll sA,
                const fp16* __restrict__ Bm, int ldb, ll sB,
                float* __restrict__ Cf, fp16* __restrict__ C16,
                int ldc, ll sC, int K, float alpha, int flags)
{
    const int bx = blockIdx.x, by = blockIdx.y, bz = blockIdx.z;
    if ((flags & 1) && 2 * bx > by) return;

    extern __shared__ char smem[];
    const uint32_t sbase = smem_u32(smem);
    const int tid = threadIdx.x;
    const int wid = tid >> 5, lane = tid & 31;
    const int wm = wid >> 2, wn = wid & 3;

    const int m0 = by * 64, n0 = bx * 128;
    int Keff = K;
    if (flags & 2) { int kb = m0 + 64; Keff = kb < K ? kb : K; }
    const int NK = Keff / 64;     // >= 1

    const char* srcA = (const char*)(A  + (ll)bz * sA + (ll)m0 * lda);
    const char* srcB = (const char*)(Bm + (ll)bz * sB + (ll)n0 * ldb);
    const ll strA = (ll)lda * 2, strB = (ll)ldb * 2;

    // loaders (smem row = 128 B, swizzle chunk ^= (row & 7)):
    // A: 64 rows x 8 chunks = 512; thread -> row tid>>2, chunks (tid&3)*2..+1
    // B: 128 rows x 8 chunks = 1024; thread -> row tid>>1, chunks (tid&1)*4..+3
    const int arow = tid >> 2;
    const int acb  = (tid & 3) * 2;
    const uint32_t armask = arow & 7;
    const uint32_t asrow = arow * 128;
    const int brow = tid >> 1;
    const int bcb  = (tid & 1) * 4;
    const uint32_t brmask = brow & 7;
    const uint32_t bsrow = brow * 128;

    auto load_stage = [&](int s, int k0) {
        const uint32_t db = sbase + s * STG16_B;
        const ll ko = (ll)k0 * 2;
        const char* ap = srcA + (ll)arow * strA + ko;
        #pragma unroll
        for (int c = 0; c < 2; c++) {
            const uint32_t cc = acb + c;
            cp16(db + asrow + ((cc ^ armask) << 4), ap + cc * 16);
        }
        const char* bp = srcB + (ll)brow * strB + ko;
        const uint32_t bb = db + MAT_A + bsrow;
        #pragma unroll
        for (int c = 0; c < 4; c++) {
            const uint32_t cc = bcb + c;
            cp16(bb + ((cc ^ brmask) << 4), bp + cc * 16);
        }
    };

    // ldmatrix base addresses (stage-relative); addr(ks) = base ^ (ks << 5)
    uint32_t rA[2], rB[2];
    {
        const int l15 = lane & 15, l4 = lane >> 4;
        #pragma unroll
        for (int mt = 0; mt < 2; mt++) {
            int r = wm * 32 + mt * 16 + l15;
            uint32_t mk = r & 7;
            rA[mt] = r * 128 + ((mk >> 1) << 5) + ((l4 ^ (mk & 1)) << 4);
        }
        const int l7 = lane & 7, l3 = (lane >> 3) & 1;
        #pragma unroll
        for (int p = 0; p < 2; p++) {
            int r = wn * 32 + (p * 2 + l4) * 8 + l7;
            uint32_t mk = r & 7;
            rB[p] = MAT_A + r * 128 + ((mk >> 1) << 5) + ((l3 ^ (mk & 1)) << 4);
        }
    }

    float acc[2][4][4] = {};

    load_stage(0, 0);  CP_COMMIT();
    load_stage(1, 64); CP_COMMIT();

    int stage = 0;
    for (int c = 0; c < NK; ++c) {
        if (c + 1 < NK) { CP_WAIT(1); } else { CP_WAIT(0); }
        __syncthreads();
        if (c + 2 < NK) {
            int ns = stage + 2; if (ns >= NSTAGE) ns -= NSTAGE;
            load_stage(ns, (c + 2) * 64);
            CP_COMMIT();
        }

        const uint32_t sb = sbase + stage * STG16_B;

        // double-buffered fragments: B per ks (parity ks&1), A per mt (parity mt&1)
        uint32_t bq[2][8], aq[2][4];
        LDSM4(bq[0][0], bq[0][1], bq[0][2], bq[0][3], sb + rB[0]);
        LDSM4(bq[0][4], bq[0][5], bq[0][6], bq[0][7], sb + rB[1]);
        LDSM4(aq[0][0], aq[0][1], aq[0][2], aq[0][3], sb + rA[0]);

        #pragma unroll
        for (int ks = 0; ks < 4; ks++) {
            const int bc = ks & 1, bn = bc ^ 1;
            if (ks < 3) {
                const uint32_t kx = (uint32_t)(ks + 1) << 5;
                LDSM4(bq[bn][0], bq[bn][1], bq[bn][2], bq[bn][3], sb + (rB[0] ^ kx));
                LDSM4(bq[bn][4], bq[bn][5], bq[bn][6], bq[bn][7], sb + (rB[1] ^ kx));
            }
            #pragma unroll
            for (int mt = 0; mt < 2; mt++) {
                const int ac = mt & 1, an = ac ^ 1;
                if (mt < 1) {
                    LDSM4(aq[an][0], aq[an][1], aq[an][2], aq[an][3],
                          sb + (rA[1] ^ ((uint32_t)ks << 5)));
                } else if (ks < 3) {
                    LDSM4(aq[an][0], aq[an][1], aq[an][2], aq[an][3],
                          sb + (rA[0] ^ ((uint32_t)(ks + 1) << 5)));
                }
                #pragma unroll
                for (int nt = 0; nt < 4; nt++)
                    MMA16816H(acc[mt][nt], aq[ac], &bq[bc][nt * 2]);
            }
        }
        if (++stage >= NSTAGE) stage = 0;
    }

    // epilogue
    const int g = lane >> 2, tg = lane & 3;
    #pragma unroll
    for (int mt = 0; mt < 2; mt++) {
        const int r = m0 + wm * 32 + mt * 16 + g;
        #pragma unroll
        for (int nt = 0; nt < 4; nt++) {
            const int col = n0 + wn * 32 + nt * 8 + 2 * tg;
            float v0 = alpha * acc[mt][nt][0];
            float v1 = alpha * acc[mt][nt][1];
            float v2 = alpha * acc[mt][nt][2];
            float v3 = alpha * acc[mt][nt][3];
            if (flags & 8) {
                *(__half2*)(C16 + (ll)bz * sC + (ll)r * ldc + col)       = __floats2half2_rn(v0, v1);
                *(__half2*)(C16 + (ll)bz * sC + (ll)(r + 8) * ldc + col) = __floats2half2_rn(v2, v3);
            } else {
                float2 p0, p1;
                p0.x = v0; p0.y = v1; p1.x = v2; p1.y = v3;
                *(float2*)(Cf + (ll)bz * sC + (ll)r * ldc + col) = p0;
                *(float2*)(Cf + (ll)bz * sC + (ll)(r + 8) * ldc + col) = p1;
            }
        }
    }
}

// ---------------- causal softmax: S f32 -> P fp16 (vectorized) ---------------
__global__ void softmax_kernel(const float* __restrict__ S, fp16* __restrict__ P)
{
    const ll row = blockIdx.x;
    const int b = (int)(row >> 12);
    const int t = (int)(row & (T_ - 1));
    const float* p = S + ((ll)b * T_ + t) * T_;
    fp16* op = P + ((ll)b * T_ + t) * T_;
    const int n  = t + 1;                 // valid entries
    const int n4 = n >> 2;                // full float4 count
    const int tb = ((t >> 7) + 1) << 7;   // zero-fill to 128-tile edge
    const int tid = threadIdx.x;
    const float4* p4 = (const float4*)p;

    __shared__ float redm[8], reds[8];

    float m = -3.402823466e38f;
    #pragma unroll
    for (int it = 0; it < 4; it++) {
        const int i = tid + it * 256;
        if (i < n4) {
            float4 v = p4[i];
            m = fmaxf(m, fmaxf(fmaxf(v.x, v.y), fmaxf(v.z, v.w)));
        }
    }
    for (int i = (n4 << 2) + tid; i < n; i += 256) m = fmaxf(m, p[i]);
    #pragma unroll
    for (int o = 16; o > 0; o >>= 1) m = fmaxf(m, __shfl_xor_sync(0xffffffffu, m, o));
    if ((tid & 31) == 0) redm[tid >> 5] = m;
    __syncthreads();
    m = redm[0];
    #pragma unroll
    for (int i = 1; i < 8; i++) m = fmaxf(m, redm[i]);

    float4 ev4[4];
    float et = 0.f;
    float s = 0.f;
    #pragma unroll
    for (int it = 0; it < 4; it++) {
        const int i = tid + it * 256;
        if (i < n4) {
            float4 v = p4[i];
            float4 e;
            e.x = __expf(v.x - m); e.y = __expf(v.y - m);
            e.z = __expf(v.z - m); e.w = __expf(v.w - m);
            ev4[it] = e;
            s += e.x + e.y + e.z + e.w;
        }
    }
    {
        const int i = (n4 << 2) + tid;
        if (i < n) { et = __expf(p[i] - m); s += et; }
    }
    #pragma unroll
    for (int o = 16; o > 0; o >>= 1) s += __shfl_xor_sync(0xffffffffu, s, o);
    if ((tid & 31) == 0) reds[tid >> 5] = s;
    __syncthreads();
    s = reds[0] + reds[1] + reds[2] + reds[3] + reds[4] + reds[5] + reds[6] + reds[7];
    const float inv = 1.0f / s;

    #pragma unroll
    for (int it = 0; it < 4; it++) {
        const int i = tid + it * 256;
        if (i < n4) {
            float4 e = ev4[it];
            __half2 h2[2];
            h2[0] = __floats2half2_rn(e.x * inv, e.y * inv);
            h2[1] = __floats2half2_rn(e.z * inv, e.w * inv);
            *(ulonglong1*)(op + 4 * i) = *(ulonglong1*)h2;
        }
    }
    {
        const int i = (n4 << 2) + tid;
        if (i < n) op[i] = __float2half_rn(et * inv);
    }
    const fp16 z = __float2half_rn(0.f);
    for (int i = n + tid; i < tb; i += 256) op[i] = z;
}

// ---------------- launch ----------------------------------------------------
extern "C" void kernel_launch(void* const* d_in, const int* in_sizes, int n_in,
                              void* d_out, int out_size)
{
    const float* x     = (const float*)d_in[0];
    const float* gamma = (const float*)d_in[2];
    const float* beta  = (const float*)d_in[3];
    const float* Wqkv  = (const float*)d_in[4];
    const float* Wproj = (const float*)d_in[5];
    float* out = (float*)d_out;

    fp16 *xn16, *wq16, *wp16, *qkv16, *vt16, *p16, *att16;
    float* S;
    cudaGetSymbolAddress((void**)&xn16,  g_xn16);
    cudaGetSymbolAddress((void**)&wq16,  g_wqkvT16);
    cudaGetSymbolAddress((void**)&wp16,  g_wprojT16);
    cudaGetSymbolAddress((void**)&qkv16, g_qkv16);
    cudaGetSymbolAddress((void**)&vt16,  g_vt16);
    cudaGetSymbolAddress((void**)&S,     g_S);
    cudaGetSymbolAddress((void**)&p16,   g_P16);
    cudaGetSymbolAddress((void**)&att16, g_att16);

    cudaFuncSetAttribute(gemm_mma16, cudaFuncAttributeMaxDynamicSharedMemorySize, GSMEM16);

    // 1. LN -> fp16
    ln_kernel<<<BT_, 128>>>(x, gamma, beta, xn16);

    // 2. weight transposes (independent)
    wtrans_kernel<<<dim3(N3_ / 32, D_ / 32), dim3(32, 8)>>>(Wqkv, D_, N3_, wq16);
    wtrans_kernel<<<dim3(D_ / 32, D_ / 32), dim3(32, 8)>>>(Wproj, D_, D_, wp16);

    // 3. QKV: xn @ WqkvT^T -> qkv fp16 [16384,1536]
    gemm_mma16<<<dim3(N3_ / 128, BT_ / 64, 1), 256, GSMEM16>>>(
        xn16, D_, 0, wq16, D_, 0,
        nullptr, qkv16, N3_, 0, D_, 1.0f, /*flags=*/8);

    // 4. V transpose per batch (fp16)
    vtrans_kernel<<<dim3(T_ / 32, D_ / 32, B_), dim3(32, 8)>>>(qkv16, vt16);

    // 5. scores: Q @ K^T * scale -> S f32 (causal tile skip)
    gemm_mma16<<<dim3(T_ / 128, T_ / 64, B_), 256, GSMEM16>>>(
        qkv16 + 0,  N3_, (ll)T_ * N3_,
        qkv16 + D_, N3_, (ll)T_ * N3_,
        S, nullptr, T_, (ll)T_ * T_, D_, SCALE_QK, /*flags=*/1);

    // 6. softmax -> P fp16 (zero-fill to tile edge)
    softmax_kernel<<<BT_, 256>>>(S, p16);

    // 7. PV: P @ VT^T -> att fp16 (causal kbound)
    gemm_mma16<<<dim3(D_ / 128, T_ / 64, B_), 256, GSMEM16>>>(
        p16, T_, (ll)T_ * T_,
        vt16, T_, (ll)D_ * T_,
        nullptr, att16, D_, (ll)T_ * D_, T_, 1.0f, /*flags=*/2 | 8);

    // 8. projection: att @ WprojT^T -> out f32
    gemm_mma16<<<dim3(D_ / 128, BT_ / 64, 1), 256, GSMEM16>>>(
        att16, D_, 0, wp16, D_, 0,
        out, nullptr, D_, 0, D_, 1.0f, /*flags=*/0);
}

// round 17
// speedup vs baseline: 1.0719x; 1.0719x over previous
#include <cuda_runtime.h>
#include <cuda_fp16.h>
#include <cstdint>
#include <math.h>

// Problem constants
#define B_  4
#define T_  4096
#define D_  512
#define BT_ (B_ * T_)          // 16384
#define N3_ (3 * D_)           // 1536
#define EPS_LN 1e-5f
#define SCALE_QK 0.04419417382415922f   // 1/sqrt(512)

typedef long long ll;
typedef __half fp16;

// ---------------- scratch (device globals) ----------------------------------
__device__ fp16  g_xn16 [(ll)BT_ * D_];       // LN output fp16
__device__ fp16  g_wqkvT16 [(ll)N3_ * D_];    // Wqkv^T fp16
__device__ fp16  g_wprojT16[(ll)D_ * D_];     // Wproj^T fp16
__device__ fp16  g_qkv16[(ll)BT_ * N3_];      // Q,K,V fp16
__device__ fp16  g_vt16 [(ll)B_ * D_ * T_];   // V transposed fp16
__device__ float g_S    [(ll)B_ * T_ * T_];   // scores f32
__device__ fp16  g_P16  [(ll)B_ * T_ * T_];   // probs fp16
__device__ fp16  g_att16[(ll)BT_ * D_];       // attention out fp16

// ---------------- PTX helpers (all base sm_103-safe) -------------------------
__device__ __forceinline__ uint32_t smem_u32(const void* p) {
    uint32_t a;
    asm("{ .reg .u64 t; cvta.to.shared.u64 t, %1; cvt.u32.u64 %0, t; }" : "=r"(a) : "l"(p));
    return a;
}
__device__ __forceinline__ void cp16(uint32_t d, const void* g) {
    asm volatile("cp.async.cg.shared.global [%0], [%1], 16;" :: "r"(d), "l"(g) : "memory");
}
#define CP_COMMIT() asm volatile("cp.async.commit_group;" ::: "memory")
#define CP_WAIT(n)  asm volatile("cp.async.wait_group %0;" :: "n"(n) : "memory")

#define LDSM4(r0, r1, r2, r3, a) \
    asm volatile("ldmatrix.sync.aligned.m8n8.x4.shared.b16 {%0,%1,%2,%3}, [%4];" \
        : "=r"(r0), "=r"(r1), "=r"(r2), "=r"(r3) : "r"(a))

#define MMA16816H(d, a, b) \
    asm volatile("mma.sync.aligned.m16n8k16.row.col.f32.f16.f16.f32 " \
        "{%0,%1,%2,%3}, {%4,%5,%6,%7}, {%8,%9}, {%0,%1,%2,%3};" \
        : "+f"((d)[0]), "+f"((d)[1]), "+f"((d)[2]), "+f"((d)[3]) \
        : "r"((a)[0]), "r"((a)[1]), "r"((a)[2]), "r"((a)[3]), "r"((b)[0]), "r"((b)[1]))

// ---------------- LayerNorm -> fp16 ------------------------------------------
__global__ void ln_kernel(const float* __restrict__ x,
                          const float* __restrict__ gamma,
                          const float* __restrict__ beta,
                          fp16* __restrict__ xn)
{
    const ll row = blockIdx.x;
    const int tid = threadIdx.x;             // 0..127
    float4 v = ((const float4*)(x + row * D_))[tid];

    float s  = v.x + v.y + v.z + v.w;
    float ss = v.x*v.x + v.y*v.y + v.z*v.z + v.w*v.w;
    #pragma unroll
    for (int o = 16; o > 0; o >>= 1) {
        s  += __shfl_xor_sync(0xffffffffu, s,  o);
        ss += __shfl_xor_sync(0xffffffffu, ss, o);
    }
    __shared__ float rs[4], rss[4];
    if ((tid & 31) == 0) { rs[tid >> 5] = s; rss[tid >> 5] = ss; }
    __syncthreads();
    s  = rs[0] + rs[1] + rs[2] + rs[3];
    ss = rss[0] + rss[1] + rss[2] + rss[3];

    const float mu   = s * (1.0f / D_);
    const float var  = ss * (1.0f / D_) - mu * mu;
    const float rstd = rsqrtf(var + EPS_LN);

    float4 g = ((const float4*)gamma)[tid];
    float4 b = ((const float4*)beta)[tid];
    __half2 h2[2];
    h2[0] = __floats2half2_rn((v.x - mu) * rstd * g.x + b.x,
                              (v.y - mu) * rstd * g.y + b.y);
    h2[1] = __floats2half2_rn((v.z - mu) * rstd * g.z + b.z,
                              (v.w - mu) * rstd * g.w + b.w);
    *(ulonglong1*)(xn + row * D_ + tid * 4) = *(ulonglong1*)h2;
}

// ---------------- weight transpose-convert: W[K,N] f32 -> Wt[N,K] fp16 -------
__global__ void wtrans_kernel(const float* __restrict__ W, int K, int N,
                              fp16* __restrict__ Tw)
{
    __shared__ float t[32][33];
    const int n0 = blockIdx.x * 32, k0 = blockIdx.y * 32;
    const int tx = threadIdx.x, ty = threadIdx.y;
    #pragma unroll
    for (int i = 0; i < 32; i += 8)
        t[ty + i][tx] = W[(ll)(k0 + ty + i) * N + n0 + tx];
    __syncthreads();
    #pragma unroll
    for (int i = 0; i < 32; i += 8)
        Tw[(ll)(n0 + ty + i) * K + k0 + tx] = __float2half_rn(t[tx][ty + i]);
}

// ---------------- V transpose: qkv16 [BT,1536] -> VT fp16 [B,512,T] ----------
__global__ void vtrans_kernel(const fp16* __restrict__ q16, fp16* __restrict__ vt)
{
    __shared__ fp16 t[32][33];
    const int s0 = blockIdx.x * 32, c0 = blockIdx.y * 32, b = blockIdx.z;
    const int tx = threadIdx.x, ty = threadIdx.y;
    const ll qb = ((ll)b * T_) * N3_ + 2 * D_;
    #pragma unroll
    for (int i = 0; i < 32; i += 8)
        t[ty + i][tx] = q16[qb + (ll)(s0 + ty + i) * N3_ + c0 + tx];
    __syncthreads();
    const ll vb = (ll)b * D_ * T_;
    #pragma unroll
    for (int i = 0; i < 32; i += 8)
        vt[vb + (ll)(c0 + ty + i) * T_ + s0 + tx] = t[tx][ty + i];
}

// ---------------- fp16 x1 NT GEMM, CTA 128x128, BK=64, warp tile 64x32 -------
// C[M,N] = alpha * A[M,K] @ B[N,K]^T, fp16 operands, fp32 accum.
// flags: 1 = causal tile skip (bx > by), 2 = causal kbound, 8 = fp16 output
// 8 warps as 2(M) x 4(N); 4x4 grid of m16n8k16 per warp; BK=64 chunks,
// 3-stage cp.async (32 KB/stage), 2 CTAs/SM, software-pipelined fragments.
#define MAT_B 16384                // 128 rows * 64 k * 2B
#define NSTAGE 3
#define STG16_B (2 * MAT_B)        // A, B = 32 KB
#define GSMEM16 (NSTAGE * STG16_B) // 96 KB

__global__ __launch_bounds__(256, 2)
void gemm_mma16(const fp16* __restrict__ A, int lda, ll sA,
                const fp16* __restrict__ Bm, int ldb, ll sB,
                float* __restrict__ Cf, fp16* __restrict__ C16,
                int ldc, ll sC, int K, float alpha, int flags)
{
    const int bx = blockIdx.x, by = blockIdx.y, bz = blockIdx.z;
    if ((flags & 1) && bx > by) return;

    extern __shared__ char smem[];
    const uint32_t sbase = smem_u32(smem);
    const int tid = threadIdx.x;
    const int wid = tid >> 5, lane = tid & 31;
    const int wm = wid >> 2, wn = wid & 3;

    const int m0 = by * 128, n0 = bx * 128;
    int Keff = K;
    if (flags & 2) { int kb = m0 + 128; Keff = kb < K ? kb : K; }
    const int NK = Keff / 64;     // >= 2 for all call sites

    const char* srcA = (const char*)(A  + (ll)bz * sA + (ll)m0 * lda);
    const char* srcB = (const char*)(Bm + (ll)bz * sB + (ll)n0 * ldb);
    const ll strA = (ll)lda * 2, strB = (ll)ldb * 2;

    // loader: 128 rows x 8 chunks (16B) per matrix; thread = row tid>>1,
    // chunks (tid&1)*4 .. +3.  smem row = 128 B, swizzle chunk ^= (row & 7).
    const int lrow = tid >> 1;
    const int lcb  = (tid & 1) * 4;
    const uint32_t lrmask = lrow & 7;
    const uint32_t lsrow = lrow * 128;

    auto load_stage = [&](int s, int k0) {
        const uint32_t db = sbase + s * STG16_B;
        const ll ko = (ll)k0 * 2;
        const char* ap = srcA + (ll)lrow * strA + ko;
        const char* bp = srcB + (ll)lrow * strB + ko;
        #pragma unroll
        for (int c = 0; c < 4; c++) {
            const uint32_t cc = lcb + c;
            const uint32_t sw = ((cc ^ lrmask) << 4);
            cp16(db + lsrow + sw,         ap + cc * 16);
            cp16(db + MAT_B + lsrow + sw, bp + cc * 16);
        }
    };

    // ldmatrix base addresses (stage-relative). The swizzled chunk index
    // (ks*2 + half) ^ mask decomposes into disjoint bit-fields, so
    // addr(ks) = base ^ (ks << 5).  6 persistent regs total.
    uint32_t rA[4], rB[2];
    {
        const int l15 = lane & 15, l4 = lane >> 4;
        #pragma unroll
        for (int mt = 0; mt < 4; mt++) {
            int r = wm * 64 + mt * 16 + l15;
            uint32_t mk = r & 7;
            rA[mt] = r * 128 + ((mk >> 1) << 5) + ((l4 ^ (mk & 1)) << 4);
        }
        const int l7 = lane & 7, l3 = (lane >> 3) & 1;
        #pragma unroll
        for (int p = 0; p < 2; p++) {
            int r = wn * 32 + (p * 2 + l4) * 8 + l7;
            uint32_t mk = r & 7;
            rB[p] = MAT_B + r * 128 + ((mk >> 1) << 5) + ((l3 ^ (mk & 1)) << 4);
        }
    }

    float acc[4][4][4] = {};

    load_stage(0, 0);  CP_COMMIT();
    load_stage(1, 64); CP_COMMIT();

    int stage = 0;
    for (int c = 0; c < NK; ++c) {
        if (c + 1 < NK) { CP_WAIT(1); } else { CP_WAIT(0); }
        __syncthreads();                 // all warps done with stage (c-1)%3
        if (c + 2 < NK) {                // its slot (c+2)%3 == (c-1)%3 is free
            int ns = stage + 2; if (ns >= NSTAGE) ns -= NSTAGE;
            load_stage(ns, (c + 2) * 64);
            CP_COMMIT();
        }

        const uint32_t sb = sbase + stage * STG16_B;

        // double-buffered fragments: B per ks (parity ks&1), A per mt (parity mt&1)
        uint32_t bq[2][8], aq[2][4];
        LDSM4(bq[0][0], bq[0][1], bq[0][2], bq[0][3], sb + rB[0]);
        LDSM4(bq[0][4], bq[0][5], bq[0][6], bq[0][7], sb + rB[1]);
        LDSM4(aq[0][0], aq[0][1], aq[0][2], aq[0][3], sb + rA[0]);

        #pragma unroll
        for (int ks = 0; ks < 4; ks++) {
            const int bc = ks & 1, bn = bc ^ 1;
            if (ks < 3) {
                const uint32_t kx = (uint32_t)(ks + 1) << 5;
                LDSM4(bq[bn][0], bq[bn][1], bq[bn][2], bq[bn][3], sb + (rB[0] ^ kx));
                LDSM4(bq[bn][4], bq[bn][5], bq[bn][6], bq[bn][7], sb + (rB[1] ^ kx));
            }
            #pragma unroll
            for (int mt = 0; mt < 4; mt++) {
                const int ac = mt & 1, an = ac ^ 1;
                if (mt < 3) {
                    LDSM4(aq[an][0], aq[an][1], aq[an][2], aq[an][3],
                          sb + (rA[mt + 1] ^ ((uint32_t)ks << 5)));
                } else if (ks < 3) {
                    LDSM4(aq[an][0], aq[an][1], aq[an][2], aq[an][3],
                          sb + (rA[0] ^ ((uint32_t)(ks + 1) << 5)));
                }
                #pragma unroll
                for (int nt = 0; nt < 4; nt++)
                    MMA16816H(acc[mt][nt], aq[ac], &bq[bc][nt * 2]);
            }
        }
        if (++stage >= NSTAGE) stage = 0;
    }

    // epilogue
    const int g = lane >> 2, tg = lane & 3;
    #pragma unroll
    for (int mt = 0; mt < 4; mt++) {
        const int r = m0 + wm * 64 + mt * 16 + g;
        #pragma unroll
        for (int nt = 0; nt < 4; nt++) {
            const int col = n0 + wn * 32 + nt * 8 + 2 * tg;
            float v0 = alpha * acc[mt][nt][0];
            float v1 = alpha * acc[mt][nt][1];
            float v2 = alpha * acc[mt][nt][2];
            float v3 = alpha * acc[mt][nt][3];
            if (flags & 8) {
                *(__half2*)(C16 + (ll)bz * sC + (ll)r * ldc + col)       = __floats2half2_rn(v0, v1);
                *(__half2*)(C16 + (ll)bz * sC + (ll)(r + 8) * ldc + col) = __floats2half2_rn(v2, v3);
            } else {
                float2 p0, p1;
                p0.x = v0; p0.y = v1; p1.x = v2; p1.y = v3;
                *(float2*)(Cf + (ll)bz * sC + (ll)r * ldc + col) = p0;
                *(float2*)(Cf + (ll)bz * sC + (ll)(r + 8) * ldc + col) = p1;
            }
        }
    }
}

// ---------------- causal softmax: S f32 -> P fp16 (single global read) -------
__global__ void softmax_kernel(const float* __restrict__ S, fp16* __restrict__ P)
{
    const ll row = blockIdx.x;
    const int b = (int)(row >> 12);
    const int t = (int)(row & (T_ - 1));
    const float* p = S + ((ll)b * T_ + t) * T_;
    fp16* op = P + ((ll)b * T_ + t) * T_;
    const int n  = t + 1;                 // valid entries
    const int n4 = n >> 2;                // full float4 count
    const int tb = ((t >> 7) + 1) << 7;   // zero-fill to 128-tile edge
    const int tid = threadIdx.x;
    const float4* p4 = (const float4*)p;

    __shared__ float redm[8], reds[8];

    // 1. single global read: cache raw values in registers + row max
    float4 ev4[4];
    float et = 0.f;
    float m = -3.402823466e38f;
    #pragma unroll
    for (int it = 0; it < 4; it++) {
        const int i = tid + it * 256;
        if (i < n4) {
            float4 v = p4[i];
            ev4[it] = v;
            m = fmaxf(m, fmaxf(fmaxf(v.x, v.y), fmaxf(v.z, v.w)));
        }
    }
    {
        const int i = (n4 << 2) + tid;
        if (i < n) { et = p[i]; m = fmaxf(m, et); }
    }
    #pragma unroll
    for (int o = 16; o > 0; o >>= 1) m = fmaxf(m, __shfl_xor_sync(0xffffffffu, m, o));
    if ((tid & 31) == 0) redm[tid >> 5] = m;
    __syncthreads();
    m = redm[0];
    #pragma unroll
    for (int i = 1; i < 8; i++) m = fmaxf(m, redm[i]);

    // 2. exp (from registers) + sum
    float s = 0.f;
    #pragma unroll
    for (int it = 0; it < 4; it++) {
        const int i = tid + it * 256;
        if (i < n4) {
            float4 v = ev4[it];
            float4 e;
            e.x = __expf(v.x - m); e.y = __expf(v.y - m);
            e.z = __expf(v.z - m); e.w = __expf(v.w - m);
            ev4[it] = e;
            s += e.x + e.y + e.z + e.w;
        }
    }
    {
        const int i = (n4 << 2) + tid;
        if (i < n) { et = __expf(et - m); s += et; }
    }
    #pragma unroll
    for (int o = 16; o > 0; o >>= 1) s += __shfl_xor_sync(0xffffffffu, s, o);
    if ((tid & 31) == 0) reds[tid >> 5] = s;
    __syncthreads();
    s = reds[0] + reds[1] + reds[2] + reds[3] + reds[4] + reds[5] + reds[6] + reds[7];
    const float inv = 1.0f / s;

    // 3. normalize + write fp16
    #pragma unroll
    for (int it = 0; it < 4; it++) {
        const int i = tid + it * 256;
        if (i < n4) {
            float4 e = ev4[it];
            __half2 h2[2];
            h2[0] = __floats2half2_rn(e.x * inv, e.y * inv);
            h2[1] = __floats2half2_rn(e.z * inv, e.w * inv);
            *(ulonglong1*)(op + 4 * i) = *(ulonglong1*)h2;
        }
    }
    {
        const int i = (n4 << 2) + tid;
        if (i < n) op[i] = __float2half_rn(et * inv);
    }
    const fp16 z = __float2half_rn(0.f);
    for (int i = n + tid; i < tb; i += 256) op[i] = z;
}

// ---------------- launch ----------------------------------------------------
extern "C" void kernel_launch(void* const* d_in, const int* in_sizes, int n_in,
                              void* d_out, int out_size)
{
    const float* x     = (const float*)d_in[0];
    const float* gamma = (const float*)d_in[2];
    const float* beta  = (const float*)d_in[3];
    const float* Wqkv  = (const float*)d_in[4];
    const float* Wproj = (const float*)d_in[5];
    float* out = (float*)d_out;

    fp16 *xn16, *wq16, *wp16, *qkv16, *vt16, *p16, *att16;
    float* S;
    cudaGetSymbolAddress((void**)&xn16,  g_xn16);
    cudaGetSymbolAddress((void**)&wq16,  g_wqkvT16);
    cudaGetSymbolAddress((void**)&wp16,  g_wprojT16);
    cudaGetSymbolAddress((void**)&qkv16, g_qkv16);
    cudaGetSymbolAddress((void**)&vt16,  g_vt16);
    cudaGetSymbolAddress((void**)&S,     g_S);
    cudaGetSymbolAddress((void**)&p16,   g_P16);
    cudaGetSymbolAddress((void**)&att16, g_att16);

    cudaFuncSetAttribute(gemm_mma16, cudaFuncAttributeMaxDynamicSharedMemorySize, GSMEM16);

    // 1. LN -> fp16
    ln_kernel<<<BT_, 128>>>(x, gamma, beta, xn16);

    // 2. weight transposes (independent)
    wtrans_kernel<<<dim3(N3_ / 32, D_ / 32), dim3(32, 8)>>>(Wqkv, D_, N3_, wq16);
    wtrans_kernel<<<dim3(D_ / 32, D_ / 32), dim3(32, 8)>>>(Wproj, D_, D_, wp16);

    // 3. QKV: xn @ WqkvT^T -> qkv fp16 [16384,1536]
    gemm_mma16<<<dim3(N3_ / 128, BT_ / 128, 1), 256, GSMEM16>>>(
        xn16, D_, 0, wq16, D_, 0,
        nullptr, qkv16, N3_, 0, D_, 1.0f, /*flags=*/8);

    // 4. V transpose per batch (fp16)
    vtrans_kernel<<<dim3(T_ / 32, D_ / 32, B_), dim3(32, 8)>>>(qkv16, vt16);

    // 5. scores: Q @ K^T * scale -> S f32 (causal tile skip)
    gemm_mma16<<<dim3(T_ / 128, T_ / 128, B_), 256, GSMEM16>>>(
        qkv16 + 0,  N3_, (ll)T_ * N3_,
        qkv16 + D_, N3_, (ll)T_ * N3_,
        S, nullptr, T_, (ll)T_ * T_, D_, SCALE_QK, /*flags=*/1);

    // 6. softmax -> P fp16 (zero-fill to tile edge)
    softmax_kernel<<<BT_, 256>>>(S, p16);

    // 7. PV: P @ VT^T -> att fp16 (causal kbound)
    gemm_mma16<<<dim3(D_ / 128, T_ / 128, B_), 256, GSMEM16>>>(
        p16, T_, (ll)T_ * T_,
        vt16, T_, (ll)D_ * T_,
        nullptr, att16, D_, (ll)T_ * D_, T_, 1.0f, /*flags=*/2 | 8);

    // 8. projection: att @ WprojT^T -> out f32
    gemm_mma16<<<dim3(D_ / 128, BT_ / 128, 1), 256, GSMEM16>>>(
        att16, D_, 0, wp16, D_, 0,
        out, nullptr, D_, 0, D_, 1.0f, /*flags=*/0);
}